// round 4
// baseline (speedup 1.0000x reference)
#include <cuda_runtime.h>

// RandomShiftsAug == integer pixel shift with edge clamp (the reference's
// bilinear weights are exactly zero given its linspace/scale arithmetic):
//   out[n,c,j,i] = x[n,c, clamp(j+sy-PAD,0,H-1), clamp(i+sx-PAD,0,W-1)]
//
// R4: register-only realignment. One warp row-slice: 22 lanes make aligned
// LDG.128 of the (vertically shifted) input row, B comes from the neighbor
// lane via __shfl_down (no L1 traffic), compose with a warp-uniform swizzle
// (sx uniform per image), patch the two edge quads with register selects,
// 21 lanes store contiguous STG.128. No SMEM, no barriers; L1tex work is the
// LDG+STG minimum.

#define C_   4
#define H_   84
#define W_   84
#define PAD_ 4
#define W4_  21
#define ROWS_PER_WARP 4

__device__ __forceinline__ float sel4(const float4& A, int i) {
    // A[clamp(i,0,3)] via selects (no local-memory array)
    return (i <= 0) ? A.x : (i == 1) ? A.y : (i == 2) ? A.z : A.w;
}

__global__ void __launch_bounds__(256) shift_warp_kernel(
    const float4* __restrict__ x4,
    const int*    __restrict__ shift,
    float4*       __restrict__ out4,
    int total_rows)                     // n*C*H
{
    int gwarp = (blockIdx.x * blockDim.x + threadIdx.x) >> 5;
    int lane  = threadIdx.x & 31;

    int row0 = gwarp * ROWS_PER_WARP;
    if (row0 >= total_rows) return;
    int rend = min(row0 + ROWS_PER_WARP, total_rows);

    for (int rho = row0; rho < rend; ++rho) {
        int nc = rho / H_;              // n*C + c
        int j  = rho - nc * H_;
        int n  = nc >> 2;

        int sx = __ldg(shift + 2 * n + 0) - PAD_;   // [-4, 4], warp-uniform
        int sy = __ldg(shift + 2 * n + 1) - PAD_;

        int ys = min(max(j + sy, 0), H_ - 1);
        int r  = sx & 3;                // warp-uniform
        int d  = (sx - r) >> 2;         // floor(sx/4) in {-1, 0, 1}

        const float4* rowp = x4 + (nc * H_ + ys) * W4_;

        float4 A = make_float4(0.f, 0.f, 0.f, 0.f);
        if (lane < W4_ + 1)             // lanes 0..21 load (lane 21 feeds lane 20's B)
            A = __ldg(rowp + min(max(lane + d, 0), W4_ - 1));

        float4 B;
        B.x = __shfl_down_sync(0xFFFFFFFFu, A.x, 1);
        B.y = __shfl_down_sync(0xFFFFFFFFu, A.y, 1);
        B.z = __shfl_down_sync(0xFFFFFFFFu, A.z, 1);
        B.w = __shfl_down_sync(0xFFFFFFFFu, A.w, 1);

        float4 v;
        if (r == 0)      v = A;
        else if (r == 1) v = make_float4(A.y, A.z, A.w, B.x);
        else if (r == 2) v = make_float4(A.z, A.w, B.x, B.y);
        else             v = make_float4(A.w, B.x, B.y, B.z);

        // Edge patches: only lane 0 (sx<0) / lane 20 (sx>0) ever clamp columns.
        if (sx < 0 && lane == 0) {
            // A = in[0..3]; out.k = in[max(k+sx,0)] = A[max(k+sx,0)]
            v.x = A.x;
            v.y = sel4(A, 1 + sx);
            v.z = sel4(A, 2 + sx);
            v.w = sel4(A, 3 + sx);
        } else if (sx > 0 && lane == W4_ - 1) {
            // A = in[80..83]; out.k = in[80 + min(k+sx,3)] = A[min(k+sx,3)]
            v.x = sel4(A, min(0 + sx, 3));
            v.y = sel4(A, min(1 + sx, 3));
            v.z = sel4(A, min(2 + sx, 3));
            v.w = A.w;
        }

        if (lane < W4_)
            out4[rho * W4_ + lane] = v;
    }
}

extern "C" void kernel_launch(void* const* d_in, const int* in_sizes, int n_in,
                              void* d_out, int out_size)
{
    const float4* x4    = (const float4*)d_in[0];
    const int*    shift = (const int*)d_in[1];
    float4*       out4  = (float4*)d_out;

    int n = in_sizes[0] / (C_ * H_ * W_);
    int total_rows = n * C_ * H_;

    int warps  = (total_rows + ROWS_PER_WARP - 1) / ROWS_PER_WARP;
    int blocks = (warps * 32 + 255) / 256;
    shift_warp_kernel<<<blocks, 256>>>(x4, shift, out4, total_rows);
}

// round 5
// speedup vs baseline: 1.1092x; 1.1092x over previous
#include <cuda_runtime.h>

// RandomShiftsAug == integer pixel shift with edge clamp (the reference's
// bilinear weights are exactly zero given its linspace/scale arithmetic):
//   out[n,c,j,i] = x[n,c, clamp(j+sy-PAD,0,H-1), clamp(i+sx-PAD,0,W-1)]
//
// R5: direct swizzle, full coverage. One thread per output float4 (1:1 with
// the contiguous store stream — no holes, no edge pass). Loads are clamped
// ALIGNED LDG.128 at quads q and q+1; consecutive threads' B-loads hit the
// same lines as neighbors' A-loads (L1 dedup), so DRAM reads stay compulsory.
// r = (4*w4+sx)&3 == sx&3 is warp-uniform per image; edge quads (at most
// thread w4==0 or w4==20 per row) are patched with register selects.

#define C_   4
#define H_   84
#define W_   84
#define PAD_ 4
#define W4_  21

__device__ __forceinline__ float sel4(const float4& A, int i) {
    return (i <= 0) ? A.x : (i == 1) ? A.y : (i == 2) ? A.z : A.w;
}

__global__ void __launch_bounds__(256) shift_direct_kernel(
    const float4* __restrict__ x4,
    const int*    __restrict__ shift,
    float4*       __restrict__ out4,
    int total4)                         // n*C*H*21
{
    int idx = blockIdx.x * blockDim.x + threadIdx.x;
    if (idx >= total4) return;

    int w4 = idx % W4_;
    int t  = idx / W4_;
    int j  = t % H_;
    int nc = t / H_;                    // n*C + c
    int n  = nc >> 2;

    int2 sh = __ldg(reinterpret_cast<const int2*>(shift) + n);
    int sx = sh.x - PAD_;               // [-4,4], uniform per image
    int sy = sh.y - PAD_;

    int ys = min(max(j + sy, 0), H_ - 1);
    const float4* row = x4 + (nc * H_ + ys) * W4_;

    int r = sx & 3;                     // warp-uniform (except image seams)
    int d = (sx - r) >> 2;              // floor(sx/4) in {-1,0,1}
    int q = min(max(w4 + d, 0), W4_ - 1);

    float4 A = __ldg(row + q);
    float4 v;
    if (r == 0) {
        v = A;
    } else {
        float4 B = __ldg(row + min(q + 1, W4_ - 1));
        if (r == 1)      v = make_float4(A.y, A.z, A.w, B.x);
        else if (r == 2) v = make_float4(A.z, A.w, B.x, B.y);
        else             v = make_float4(A.w, B.x, B.y, B.z);
    }

    // Edge patches (A is the clamped edge quad in both cases):
    if (sx < 0 && w4 == 0) {
        // out[k] = in[max(k+sx, 0)] = A[max(k+sx, 0)]
        v.x = A.x;
        v.y = sel4(A, 1 + sx);
        v.z = sel4(A, 2 + sx);
        v.w = sel4(A, 3 + sx);
    } else if (sx > 0 && w4 == W4_ - 1) {
        // out[k] = in[80 + min(k+sx, 3)] = A[min(k+sx, 3)]
        v.x = sel4(A, min(0 + sx, 3));
        v.y = sel4(A, min(1 + sx, 3));
        v.z = sel4(A, min(2 + sx, 3));
        v.w = A.w;
    }

    out4[idx] = v;
}

extern "C" void kernel_launch(void* const* d_in, const int* in_sizes, int n_in,
                              void* d_out, int out_size)
{
    const float4* x4    = (const float4*)d_in[0];
    const int*    shift = (const int*)d_in[1];
    float4*       out4  = (float4*)d_out;

    int n = in_sizes[0] / (C_ * H_ * W_);
    int total4 = n * C_ * H_ * W4_;

    int threads = 256;
    int blocks  = (total4 + threads - 1) / threads;
    shift_direct_kernel<<<blocks, threads>>>(x4, shift, out4, total4);
}

// round 10
// speedup vs baseline: 1.2287x; 1.1076x over previous
#include <cuda_runtime.h>
#include <cstdint>

// RandomShiftsAug == integer pixel shift with edge clamp (reference's bilinear
// weights are exactly zero given its linspace/scale arithmetic):
//   out[n,c,j,i] = x[n,c, clamp(j+sy-PAD,0,H-1), clamp(i+sx-PAD,0,W-1)]
//
// R10: one CTA per image n (4 channel planes share the same shift), cp.async
// double-buffered pipeline: plane p+1's GMEM->SMEM bulk copy is in flight
// while plane p is pad-filled, swizzled and stored. Removes the R3 phase
// serialization (load / barrier / swizzle) that left DRAM at 62% with
// issue at 23%.

#define C_    4
#define W_    84
#define H_    84
#define PAD_  4
#define W4_   21
#define RP_   96                       // padded SMEM row (floats): 4 pad | 84 | 4 pad | 4 align
#define NBLK  (H_ * W4_)               // 1764 float4 per plane
#define BUF_FLOATS (H_ * RP_)          // 8064 floats = 32256 B
#define SMEM_BYTES (2 * BUF_FLOATS * 4) // 64512 B (dynamic)

__device__ __forceinline__ void cp16(float* dst, const float4* src) {
    uint32_t d = (uint32_t)__cvta_generic_to_shared(dst);
    asm volatile("cp.async.cg.shared.global [%0], [%1], 16;"
                 :: "r"(d), "l"(src) : "memory");
}
__device__ __forceinline__ void cp_commit() {
    asm volatile("cp.async.commit_group;" ::: "memory");
}
template <int N>
__device__ __forceinline__ void cp_wait() {
    asm volatile("cp.async.wait_group %0;" :: "n"(N) : "memory");
}

__global__ void __launch_bounds__(256) shift_pipe_kernel(
    const float4* __restrict__ x4,
    const int*    __restrict__ shift,
    float4*       __restrict__ out4)
{
    extern __shared__ float sb[];      // 2 buffers of H_*RP_ floats

    const int n   = blockIdx.x;
    const int tid = threadIdx.x;

    int2 sh = __ldg(reinterpret_cast<const int2*>(shift) + n);
    const int sx = sh.x - PAD_;        // [-4, 4]
    const int sy = sh.y - PAD_;

    const float4* base_in  = x4  + (size_t)n * C_ * NBLK;
    float4*       base_out = out4 + (size_t)n * C_ * NBLK;

    // ---- stage plane p into buffer b via cp.async (one commit group) ----
    auto issue = [&](int p, int b) {
        const float4* in4 = base_in + p * NBLK;
        float* buf = sb + b * BUF_FLOATS;
        #pragma unroll
        for (int it = 0; it < 7; ++it) {
            int m = tid + it * 256;
            if (m < NBLK) {
                int row = m / W4_;
                int w4  = m - row * W4_;
                cp16(buf + row * RP_ + 4 + 4 * w4, in4 + m);
            }
        }
        cp_commit();
    };

    // ---- pad-fill + swizzle + store plane p from buffer b ----
    auto process = [&](int p, int b) {
        float* buf = sb + b * BUF_FLOATS;
        if (tid < H_) {                 // edge-clamp pads for this row
            float4* prow = reinterpret_cast<float4*>(buf + tid * RP_);
            float l = buf[tid * RP_ + 4];
            float r = buf[tid * RP_ + 87];
            prow[0]  = make_float4(l, l, l, l);    // floats 0..3
            prow[22] = make_float4(r, r, r, r);    // floats 88..91
        }
        __syncthreads();

        float4* o4 = base_out + p * NBLK;
        #pragma unroll
        for (int it = 0; it < 7; ++it) {
            int m = tid + it * 256;
            if (m < NBLK) {
                int j  = m / W4_;
                int w4 = m - j * W4_;
                int ys = min(max(j + sy, 0), H_ - 1);
                int pp = 4 + 4 * w4 + sx;          // [0, 88]
                int q  = pp >> 2;
                int r  = pp & 3;                   // warp-uniform (sx per image)
                const float4* row4 = reinterpret_cast<const float4*>(buf + ys * RP_);
                float4 A = row4[q];
                float4 v;
                if (r == 0) {
                    v = A;
                } else {
                    float4 B = row4[q + 1];
                    if (r == 1)      v = make_float4(A.y, A.z, A.w, B.x);
                    else if (r == 2) v = make_float4(A.z, A.w, B.x, B.y);
                    else             v = make_float4(A.w, B.x, B.y, B.z);
                }
                o4[m] = v;
            }
        }
        __syncthreads();                // buffer may be overwritten after this
    };

    issue(0, 0);
    issue(1, 1);
    cp_wait<1>(); __syncthreads();      // g0 (plane 0) complete
    process(0, 0);
    issue(2, 0);
    cp_wait<1>(); __syncthreads();      // g1 complete
    process(1, 1);
    issue(3, 1);
    cp_wait<1>(); __syncthreads();      // g2 complete
    process(2, 0);
    cp_wait<0>(); __syncthreads();      // g3 complete
    process(3, 1);
}

extern "C" void kernel_launch(void* const* d_in, const int* in_sizes, int n_in,
                              void* d_out, int out_size)
{
    const float4* x4    = (const float4*)d_in[0];
    const int*    shift = (const int*)d_in[1];
    float4*       out4  = (float4*)d_out;

    int n = in_sizes[0] / (C_ * H_ * W_);

    static bool attr_set = false;
    if (!attr_set) {
        cudaFuncSetAttribute(shift_pipe_kernel,
                             cudaFuncAttributeMaxDynamicSharedMemorySize,
                             SMEM_BYTES);
        attr_set = true;
    }
    shift_pipe_kernel<<<n, 256, SMEM_BYTES>>>(x4, shift, out4);
}